// round 15
// baseline (speedup 1.0000x reference)
#include <cuda_runtime.h>
#include <cuda_fp16.h>
#include <cstdint>
#include <cstddef>

// Problem constants
#define BSZ 64
#define TT  512
#define ISZ 512
#define HSZ 1024
#define G4  4096
#define OSZ 128
#define NCTA 128
#define NTHR 128

typedef unsigned long long u64;

// ---------------------------------------------------------------------------
// Static device scratch
// g_gxf : x-gates fragment order: [t][cta(128)][gate(4)][nt(2)][slot(128)] float2
// g_h16 : h fp16 chunk images [buf][chunk(8)][q(2)][b_local(32)][k(128)] swizzled
// g_x16 : x fp16 block images [mt(256)*8+kc][m(128)][k(64)] swizzled
// g_w16 : W_ih fp16 block images [nt(32)*8+kc][n(128)][k(64)] swizzled
// g_seq : per-producer step sequence numbers, ONE 128B LINE EACH
//         slot (q, jt) at g_seq[(q*64+jt)*32]; producer stores t+1 when its
//         h^{t+1} slice is published (plain st.release, no RMW).
// ---------------------------------------------------------------------------
__device__ __align__(16) float  g_gxf[(size_t)TT * 128 * 4 * 2 * 128 * 2];
__device__ __align__(16) __half g_h16[2][65536];
__device__ __align__(16) __half g_x16[(size_t)2048 * 8192];
__device__ __align__(16) __half g_w16[(size_t)256 * 8192];
__device__ __align__(16) float  g_hfin[BSZ * HSZ];
__device__ __align__(128) unsigned g_seq[2 * 64 * 32];

// ---------------------------------------------------------------------------
// Helpers
// ---------------------------------------------------------------------------
__device__ __forceinline__ unsigned pkh(float a, float b) {   // low=h(a), high=h(b)
    unsigned r; asm("cvt.rn.f16x2.f32 %0, %1, %2;" : "=r"(r) : "f"(b), "f"(a)); return r;
}
__device__ __forceinline__ unsigned smem_u32(const void* p) {
    unsigned a;
    asm("{ .reg .u64 t; cvta.to.shared.u64 t, %1; cvt.u32.u64 %0, t; }" : "=r"(a) : "l"(p));
    return a;
}
__device__ __forceinline__ void seq_rel(unsigned* f, unsigned v) {
    asm volatile("st.release.gpu.global.u32 [%0], %1;" :: "l"(f), "r"(v) : "memory");
}
__device__ __forceinline__ unsigned flag_acq(const unsigned* f) {
    unsigned v;
    asm volatile("ld.acquire.gpu.global.u32 %0, [%1];" : "=r"(v) : "l"(f) : "memory");
    return v;
}
__device__ __forceinline__ void mbar_init(unsigned a, unsigned cnt) {
    asm volatile("mbarrier.init.shared.b64 [%0], %1;" :: "r"(a), "r"(cnt) : "memory");
}
__device__ __forceinline__ void mbar_expect(unsigned a, unsigned bytes) {
    asm volatile("mbarrier.arrive.expect_tx.shared.b64 _, [%0], %1;" :: "r"(a), "r"(bytes) : "memory");
}
__device__ __forceinline__ void mbar_wait(unsigned a, unsigned parity) {
    asm volatile(
        "{\n\t.reg .pred P;\n\t"
        "WL_%=:\n\t"
        "mbarrier.try_wait.parity.acquire.cta.shared::cta.b64 P, [%0], %1, 0x989680;\n\t"
        "@P bra.uni WD_%=;\n\t"
        "bra.uni WL_%=;\n\t"
        "WD_%=:\n\t}"
        :: "r"(a), "r"(parity) : "memory");
}
__device__ __forceinline__ void bulk_g2s(unsigned sdst, const void* gsrc, unsigned bytes, unsigned mbar) {
    asm volatile("cp.async.bulk.shared::cluster.global.mbarrier::complete_tx::bytes [%0], [%1], %2, [%3];"
                 :: "r"(sdst), "l"(gsrc), "r"(bytes), "r"(mbar) : "memory");
}
__device__ __forceinline__ void ldsm4(unsigned* r, unsigned addr) {
    asm volatile("ldmatrix.sync.aligned.m8n8.x4.shared.b16 {%0,%1,%2,%3}, [%4];"
                 : "=r"(r[0]), "=r"(r[1]), "=r"(r[2]), "=r"(r[3]) : "r"(addr));
}
__device__ __forceinline__ void mma16816(float* d, const unsigned* a, unsigned b0, unsigned b1) {
    asm volatile(
        "mma.sync.aligned.m16n8k16.row.col.f32.f16.f16.f32 "
        "{%0,%1,%2,%3}, {%4,%5,%6,%7}, {%8,%9}, {%0,%1,%2,%3};"
        : "+f"(d[0]), "+f"(d[1]), "+f"(d[2]), "+f"(d[3])
        : "r"(a[0]), "r"(a[1]), "r"(a[2]), "r"(a[3]), "r"(b0), "r"(b1));
}
__device__ __forceinline__ float sigm(float x) { return 1.f / (1.f + __expf(-x)); }
__device__ __forceinline__ float tanh_fast(float x) {
    float e = __expf(2.f * x);
    return 1.f - 2.f / (e + 1.f);
}

// ---------------------------------------------------------------------------
// Zero h buffer 0 and sequence slots
// ---------------------------------------------------------------------------
__global__ void k_zero() {
    int i = blockIdx.x * blockDim.x + threadIdx.x;
    if (i < 32768) ((unsigned*)&g_h16[0][0])[i] = 0u;
    if (i < 2 * 64 * 32) g_seq[i] = 0u;
}

// ---------------------------------------------------------------------------
// Prep: x -> fp16 block images; W_ih -> fp16 block images (swizzled)
// ---------------------------------------------------------------------------
#define NXSEG (32768 * 64)
#define NWSEG (4096 * 64)
__global__ __launch_bounds__(256)
void k_prep(const float* __restrict__ x, const float* __restrict__ Wih) {
    int s0 = blockIdx.x * blockDim.x + threadIdx.x;
    const int stride = gridDim.x * blockDim.x;
    for (int s = s0; s < NXSEG + NWSEG; s += stride) {
        const float* src;
        char* dst;
        unsigned off;
        if (s < NXSEG) {
            int m  = s >> 6;
            int sk = s & 63;
            int b = m & 63, t = m >> 6;
            src = x + ((size_t)b * TT + t) * ISZ + sk * 8;
            int mt = m >> 7, ml = m & 127, kc = sk >> 3, seg = sk & 7;
            off = (unsigned)(mt * 8 + kc) * 16384u + (unsigned)ml * 128u
                + (unsigned)((seg ^ (ml & 7)) * 16);
            dst = (char*)g_x16;
        } else {
            int sw = s - NXSEG;
            int n  = sw >> 6;
            int sk = sw & 63;
            src = Wih + (size_t)n * ISZ + sk * 8;
            int nt = n >> 7, nl = n & 127, kc = sk >> 3, seg = sk & 7;
            off = (unsigned)(nt * 8 + kc) * 16384u + (unsigned)nl * 128u
                + (unsigned)((seg ^ (nl & 7)) * 16);
            dst = (char*)g_w16;
        }
        float4 v0 = *(const float4*)(src);
        float4 v1 = *(const float4*)(src + 4);
        uint4 hi = make_uint4(pkh(v0.x, v0.y), pkh(v0.z, v0.w),
                              pkh(v1.x, v1.y), pkh(v1.z, v1.w));
        *(uint4*)(dst + off) = hi;
    }
}

// ---------------------------------------------------------------------------
// Input GEMM via mma.sync fp16 (single product), 2-stage pipeline.
// CTA tile: 128 gates (nt) x 128 bt (mt), K=512 in 8 chunks of 64.
// Epilogue writes gx in fragment order for the batch-split recurrence.
// ---------------------------------------------------------------------------
#define IG_STAGE  32768
#define IG_SMEM  (2 * IG_STAGE + 512)
__global__ __launch_bounds__(256, 2)
void k_input_mma(const float* __restrict__ bih, const float* __restrict__ bhh) {
    extern __shared__ __align__(16) char smem[];
    const unsigned sb = smem_u32(smem);
    float* sbias = (float*)(smem + 2 * IG_STAGE);
    __shared__ __align__(8) u64 s_mbar[2];

    const int nt = blockIdx.x;    // 0..31
    const int mt = blockIdx.y;    // 0..255
    const int tid  = threadIdx.x;
    const int w    = tid >> 5;
    const int lane = tid & 31;
    const int wgate = (w >> 1) * 32;
    const int wm    = (w & 1) * 64;

    if (tid < 128) {
        int n = nt * 128 + tid;
        sbias[tid] = bih[n] + bhh[n];
    }
    if (tid == 0) { mbar_init(smem_u32(&s_mbar[0]), 1); mbar_init(smem_u32(&s_mbar[1]), 1); }
    __syncthreads();
    unsigned mb[2] = { smem_u32(&s_mbar[0]), smem_u32(&s_mbar[1]) };
    unsigned ph[2] = {0u, 0u};

    auto issue = [&](int kc) {
        int st = kc & 1;
        unsigned base = sb + (unsigned)st * IG_STAGE;
        size_t woff = ((size_t)nt * 8 + kc) * 16384;
        size_t xoff = ((size_t)mt * 8 + kc) * 16384;
        mbar_expect(mb[st], IG_STAGE);
        bulk_g2s(base,          (const char*)g_w16 + woff, 16384u, mb[st]);
        bulk_g2s(base + 16384u, (const char*)g_x16 + xoff, 16384u, mb[st]);
    };
    if (tid == 0) { issue(0); issue(1); }

    float d[2][8][4];
#pragma unroll
    for (int i = 0; i < 2; ++i)
#pragma unroll
        for (int j = 0; j < 8; ++j)
#pragma unroll
            for (int r = 0; r < 4; ++r) d[i][j][r] = 0.f;

    const int rA0 = wgate + (lane & 15);
    const int rA1 = rA0 + 16;
    const unsigned aSegSel = (unsigned)((lane >> 4) & 1);
    const int rBbase = wm + (lane & 7) + ((lane >> 4) & 1) * 8;
    const unsigned bSegSel = (unsigned)((lane >> 3) & 1);

    for (int kc = 0; kc < 8; ++kc) {
        const int st = kc & 1;
        mbar_wait(mb[st], ph[st] & 1u);
        ph[st]++;
        unsigned base = sb + (unsigned)st * IG_STAGE;
        unsigned Aim = base, Bim = base + 16384u;
#pragma unroll
        for (int ks = 0; ks < 4; ++ks) {
            unsigned Ah0[4], Ah1[4];
            unsigned segA0 = ((unsigned)(ks * 2) + aSegSel);
            ldsm4(Ah0, Aim + (unsigned)rA0 * 128u + ((segA0 ^ (unsigned)(rA0 & 7)) << 4));
            ldsm4(Ah1, Aim + (unsigned)rA1 * 128u + ((segA0 ^ (unsigned)(rA1 & 7)) << 4));
#pragma unroll
            for (int np = 0; np < 4; ++np) {
                int rB = rBbase + np * 16;
                unsigned segB = ((unsigned)(ks * 2) + bSegSel) ^ (unsigned)(rB & 7);
                unsigned Bh[4];
                ldsm4(Bh, Bim + (unsigned)rB * 128u + (segB << 4));
                mma16816(d[0][np * 2],     Ah0, Bh[0], Bh[1]);
                mma16816(d[0][np * 2 + 1], Ah0, Bh[2], Bh[3]);
                mma16816(d[1][np * 2],     Ah1, Bh[0], Bh[1]);
                mma16816(d[1][np * 2 + 1], Ah1, Bh[2], Bh[3]);
            }
        }
        __syncthreads();
        if (kc + 2 < 8 && tid == 0) issue(kc + 2);
    }

    // epilogue: write gx in fragment order (batch-split mapping)
    const int fg  = lane >> 2;
    const int tig = lane & 3;
#pragma unroll
    for (int mt2 = 0; mt2 < 2; ++mt2) {
#pragma unroll
        for (int rr = 0; rr < 2; ++rr) {
            int row = wgate + mt2 * 16 + fg + rr * 8;
            int n = nt * 128 + row;
            int gate = n >> 10, junit = n & 1023;
            int jtv = junit >> 4, jl = junit & 15;
            int w2 = jl >> 3, fgl = jl & 7;
            float bias = sbias[row];
#pragma unroll
            for (int j = 0; j < 8; ++j) {
                int mcol = wm + (j >> 1) * 16 + (j & 1) * 8 + tig * 2;
                int tt = mt * 2 + (mcol >> 6);
                int b  = mcol & 63;
                int q  = b >> 5, bl = b & 31;
                int wb = bl >> 4, rem = bl & 15;
                int ntv = rem >> 3, tigl = (rem >> 1) & 3;
                int cta  = jtv * 2 + q;
                int slot = (wb * 2 + w2) * 32 + fgl * 4 + tigl;
                size_t idx = ((((size_t)tt * 128 + cta) * 4 + gate) * 2 + ntv) * 128 + slot;
                ((float2*)g_gxf)[idx] = make_float2(d[mt2][j][rr * 2] + bias,
                                                    d[mt2][j][rr * 2 + 1] + bias);
            }
        }
    }
}

// ---------------------------------------------------------------------------
// SMEM layout for k_lstm (bytes):
//   W : 64 x (1024 fp16 + 8 pad) stride 2064             [0      , 132096)
//   B : 8 bufs x 8192 (swizzled half-chunk images)       [132096 , 197632)
// ---------------------------------------------------------------------------
#define W_STRIDE   2064
#define B_OFF      132096
#define B_BUFSZ    8192
#define SMEM_TOTAL 197632

// ---------------------------------------------------------------------------
// Persistent tensor-core LSTM, batch-split (R14 structure).
// Sync: per-producer padded sequence slots (st.release / ld.acquire, no RMW).
// Issuer lane for chunk c polls its 8 producers' slots until all >= t.
// CTA publishes once per step (tid0, after __syncthreads).
// ---------------------------------------------------------------------------
__global__ __launch_bounds__(NTHR, 1)
void k_lstm(const float* __restrict__ Whh) {
    extern __shared__ __align__(16) char smem[];
    const unsigned sb = smem_u32(smem);
    __shared__ __align__(8) u64 s_mbar[8];

    const int bid  = blockIdx.x;
    const int jt   = bid >> 1;           // 0..63
    const int q    = bid & 1;            // batch half
    const int tid  = threadIdx.x;
    const int w    = tid >> 5;
    const int lane = tid & 31;
    const int kw   = jt >> 3;            // chunk this CTA produces into
    const int cta  = jt * 2 + q;

    // ---- one-time: W_hh rows -> SMEM fp16 (row lr = gate*16 + jl) ----
#pragma unroll
    for (int it = 0; it < 128; ++it) {
        int f   = tid + it * NTHR;       // 16384 float4
        int row = f >> 8;                // 0..63
        int k4  = (f & 255) << 2;
        int gate = row >> 4, jl = row & 15;
        const float* src = Whh + (size_t)(gate * HSZ + jt * 16 + jl) * HSZ + k4;
        float4 v = *(const float4*)src;
        uint2 hi = make_uint2(pkh(v.x, v.y), pkh(v.z, v.w));
        *(uint2*)(smem + (size_t)row * W_STRIDE + k4 * 2) = hi;
    }

    if (tid == 0)
#pragma unroll
        for (int m = 0; m < 8; ++m) mbar_init(smem_u32(&s_mbar[m]), 1);
    __syncthreads();

    unsigned mb[8];
#pragma unroll
    for (int m = 0; m < 8; ++m) mb[m] = smem_u32(&s_mbar[m]);

    const int w2 = w & 1, wb = w >> 1;
    const int jj0 = w2 * 8;
    // A: scattered rows (gate-interleaved): tile0 rows = gate{0,1} of jj0+(lane&7)
    const unsigned aRow  = (unsigned)(((lane >> 3) & 1) * 16 + jj0 + (lane & 7));
    const unsigned aBase = sb + aRow * W_STRIDE + ((lane >> 4) & 1) * 16u;
    // B: local batches [16wb, 16wb+16)
    const unsigned bRow  = (unsigned)(wb * 16 + (lane & 7) + ((lane >> 4) & 1) * 8);
    const unsigned bHalf = (unsigned)((lane >> 3) & 1);
    const unsigned bMask = bRow & 7u;
    const unsigned bRowOff = bRow * 256u;

    const int fg  = lane >> 2;           // jj = jj0 + fg owned by this thread
    const int tig = lane & 3;
    float cc[4] = {0.f, 0.f, 0.f, 0.f};  // cells: [nt*2+e], b_local = 16wb+8nt+2tig+e

    // h-image store offsets for the 4 cells
    unsigned hoff[4];
    const int kl = (jt & 7) * 16 + jj0 + fg;   // k index within chunk
#pragma unroll
    for (int m = 0; m < 4; ++m) {
        int bl = wb * 16 + (m >> 1) * 8 + tig * 2 + (m & 1);
        unsigned seg = (unsigned)((kl >> 3) ^ (bl & 7));
        hoff[m] = (unsigned)(kw * 2 + q) * 8192u + (unsigned)bl * 256u
                + (seg << 4) + (unsigned)(kl & 7) * 2u;
    }

    // issue streams: lanes 0 and 16 of each warp handle chunks w and w+4
    const int myc = w + ((lane >> 4) & 1) * 4;
    const bool issuer = ((lane & 15) == 0);
    // producer seq slots for my chunk: jt' in [8*myc, 8*myc+8), half q
    unsigned* const seq_base = &g_seq[(q * 64 + myc * 8) * 32];
    unsigned* const my_seq   = &g_seq[(q * 64 + jt) * 32];

    for (int t = 0; t < TT; ++t) {
        const unsigned par = (unsigned)(t & 1);

        // ---- gx prefetch (fragment order, 8 coalesced LDG.64) ----
        float2 gxv[8];
        {
            const float2* gbase = (const float2*)g_gxf + ((size_t)t * 128 + cta) * 8 * 128 + tid;
#pragma unroll
            for (int gn = 0; gn < 8; ++gn) gxv[gn] = gbase[gn * 128];
        }

        // ---- 8 parallel spin+issue streams (lanes 0,16 of each warp) ----
        if (issuer) {
            if (t) {
                const unsigned tgt = (unsigned)t;
                for (;;) {
                    unsigned mn = 0xFFFFFFFFu;
#pragma unroll
                    for (int j = 0; j < 8; ++j) {
                        unsigned v = flag_acq(seq_base + j * 32);
                        mn = v < mn ? v : mn;
                    }
                    if (mn >= tgt) break;
                }
            }
            mbar_expect(mb[myc], B_BUFSZ);
            bulk_g2s(sb + B_OFF + (unsigned)myc * B_BUFSZ,
                     (const char*)&g_h16[par][0] + (size_t)(myc * 2 + q) * B_BUFSZ,
                     B_BUFSZ, mb[myc]);
        }

        float d[2][2][4];
#pragma unroll
        for (int mt = 0; mt < 2; ++mt)
#pragma unroll
            for (int nt2 = 0; nt2 < 2; ++nt2)
#pragma unroll
                for (int r = 0; r < 4; ++r) d[mt][nt2][r] = 0.f;

        for (int c = 0; c < 8; ++c) {
            mbar_wait(mb[c], par);
            const unsigned ahi  = aBase + (unsigned)c * 256u;
            const unsigned ahi2 = ahi + 32u * W_STRIDE;
            const unsigned bbuf = sb + B_OFF + (unsigned)c * B_BUFSZ + bRowOff;
#pragma unroll
            for (int ks = 0; ks < 8; ++ks) {
                unsigned A0[4], A1[4], B[4];
                unsigned seg = ((unsigned)(ks * 2) + bHalf) ^ bMask;
                ldsm4(B,  bbuf + (seg << 4));
                ldsm4(A0, ahi  + ks * 32u);
                ldsm4(A1, ahi2 + ks * 32u);
                mma16816(d[0][0], A0, B[0], B[1]);
                mma16816(d[0][1], A0, B[2], B[3]);
                mma16816(d[1][0], A1, B[0], B[1]);
                mma16816(d[1][1], A1, B[2], B[3]);
            }
        }

        // ---- register-resident activations (4 cells) ----
        __half* hbase = &g_h16[(t + 1) & 1][0];
#pragma unroll
        for (int nt2 = 0; nt2 < 2; ++nt2) {
#pragma unroll
            for (int e = 0; e < 2; ++e) {
                int m = nt2 * 2 + e;
                float gi = d[0][nt2][e]     + (e ? gxv[0 + nt2].y : gxv[0 + nt2].x);
                float gf = d[0][nt2][2 + e] + (e ? gxv[2 + nt2].y : gxv[2 + nt2].x);
                float gg = d[1][nt2][e]     + (e ? gxv[4 + nt2].y : gxv[4 + nt2].x);
                float go = d[1][nt2][2 + e] + (e ? gxv[6 + nt2].y : gxv[6 + nt2].x);
                float si = sigm(gi), sf = sigm(gf), so = sigm(go);
                cc[m] = sf * cc[m] + si * tanh_fast(gg);
                float hv = so * tanh_fast(cc[m]);
                *(__half*)((char*)hbase + hoff[m]) = __float2half_rn(hv);
                if (t == TT - 1) {
                    int bl = wb * 16 + nt2 * 8 + tig * 2 + e;
                    g_hfin[(size_t)(32 * q + bl) * HSZ + jt * 16 + jj0 + fg] = hv;
                }
            }
        }

        // ---- per-CTA publish: one plain release store, own 128B line ----
        __syncthreads();                       // all warps' h stores done; also
                                               // protects B buffers for reuse
        if (tid == 0) seq_rel(my_seq, (unsigned)(t + 1));
    }
}

// ---------------------------------------------------------------------------
// Classifier
// ---------------------------------------------------------------------------
__global__ __launch_bounds__(128)
void k_classifier(const float* __restrict__ Wclf,
                  const float* __restrict__ bclf,
                  float* __restrict__ out) {
    int b = blockIdx.x;
    int o = threadIdx.x;
    __shared__ float hsh[HSZ];
    for (int k = threadIdx.x; k < HSZ; k += 128) hsh[k] = g_hfin[(size_t)b * HSZ + k];
    __syncthreads();
    const float* wp = Wclf + (size_t)o * HSZ;
    float acc = 0.f;
#pragma unroll 4
    for (int k = 0; k < HSZ; k += 4) {
        float4 wv = *(const float4*)(wp + k);
        acc += wv.x * hsh[k] + wv.y * hsh[k + 1] + wv.z * hsh[k + 2] + wv.w * hsh[k + 3];
    }
    out[b * OSZ + o] = acc + bclf[o];
}

// ---------------------------------------------------------------------------
// Launch (graph-capturable: kernel launches only)
// ---------------------------------------------------------------------------
extern "C" void kernel_launch(void* const* d_in, const int* in_sizes, int n_in,
                              void* d_out, int out_size) {
    const float* x    = (const float*)d_in[0];
    const float* Wih  = (const float*)d_in[1];
    const float* Whh  = (const float*)d_in[2];
    const float* bih  = (const float*)d_in[3];
    const float* bhh  = (const float*)d_in[4];
    const float* Wclf = (const float*)d_in[5];
    const float* bclf = (const float*)d_in[6];
    float* out = (float*)d_out;

    cudaFuncSetAttribute(k_input_mma, cudaFuncAttributeMaxDynamicSharedMemorySize, IG_SMEM);
    cudaFuncSetAttribute(k_lstm,      cudaFuncAttributeMaxDynamicSharedMemorySize, SMEM_TOTAL);

    k_zero<<<256, 256>>>();
    k_prep<<<2304, 256>>>(x, Wih);
    k_input_mma<<<dim3(32, 256), 256, IG_SMEM>>>(bih, bhh);
    k_lstm<<<NCTA, NTHR, SMEM_TOTAL>>>(Whh);
    k_classifier<<<64, 128>>>(Wclf, bclf, out);
}

// round 16
// speedup vs baseline: 1.1783x; 1.1783x over previous
#include <cuda_runtime.h>
#include <cuda_fp16.h>
#include <cstdint>
#include <cstddef>

// Problem constants
#define BSZ 64
#define TT  512
#define ISZ 512
#define HSZ 1024
#define G4  4096
#define OSZ 128
#define NCTA 128
#define NTHR 128

typedef unsigned long long u64;

// ---------------------------------------------------------------------------
// Static device scratch
// g_gxf : x-gates fragment order: [t][cta(128)][gate(4)][nt(2)][slot(128)] float2
// g_hf  : h fp16 in MMA B-FRAGMENT order:
//         uint4[buf(2)][q(2)][wb(2)][chunk(8)][ks(8)][lane(32)]
//         lane's uint4 = {B0: h[k=2(lane&3)+{0,1}][b=lane>>2],  B1: k+8,
//                         B2: b+8,                              B3: b+8,k+8}
//         (b is local to (q,wb): b_global = q*32 + wb*16 + b)
// g_x16 : x fp16 block images [mt(256)*8+kc][m(128)][k(64)] swizzled
// g_w16 : W_ih fp16 block images [nt(32)*8+kc][n(128)][k(64)] swizzled
// ---------------------------------------------------------------------------
__device__ __align__(16) float  g_gxf[(size_t)TT * 128 * 4 * 2 * 128 * 2];
__device__ __align__(16) uint4  g_hf[2 * 2 * 2 * 8 * 8 * 32];     // 256KB
__device__ __align__(16) __half g_x16[(size_t)2048 * 8192];
__device__ __align__(16) __half g_w16[(size_t)256 * 8192];
__device__ __align__(16) float  g_hfin[BSZ * HSZ];
__device__ unsigned g_donec[16];   // per (chunk, q) publish counters (32/step)

// strides for g_hf in uint4 units
#define HF_BUF 8192
#define HF_Q   4096
#define HF_WB  2048
#define HF_C   256
#define HF_KS  32

// ---------------------------------------------------------------------------
// Helpers
// ---------------------------------------------------------------------------
__device__ __forceinline__ unsigned pkh(float a, float b) {   // low=h(a), high=h(b)
    unsigned r; asm("cvt.rn.f16x2.f32 %0, %1, %2;" : "=r"(r) : "f"(b), "f"(a)); return r;
}
__device__ __forceinline__ unsigned smem_u32(const void* p) {
    unsigned a;
    asm("{ .reg .u64 t; cvta.to.shared.u64 t, %1; cvt.u32.u64 %0, t; }" : "=r"(a) : "l"(p));
    return a;
}
__device__ __forceinline__ void flag_rel(unsigned* f) {
    asm volatile("red.release.gpu.global.add.u32 [%0], %1;" :: "l"(f), "r"(1u) : "memory");
}
__device__ __forceinline__ unsigned flag_acq(const unsigned* f) {
    unsigned v;
    asm volatile("ld.acquire.gpu.global.u32 %0, [%1];" : "=r"(v) : "l"(f) : "memory");
    return v;
}
__device__ __forceinline__ uint4 ldcg4(const uint4* p) {
    uint4 v;
    asm volatile("ld.global.cg.v4.u32 {%0,%1,%2,%3}, [%4];"
                 : "=r"(v.x), "=r"(v.y), "=r"(v.z), "=r"(v.w) : "l"(p));
    return v;
}
__device__ __forceinline__ void mbar_init(unsigned a, unsigned cnt) {
    asm volatile("mbarrier.init.shared.b64 [%0], %1;" :: "r"(a), "r"(cnt) : "memory");
}
__device__ __forceinline__ void mbar_expect(unsigned a, unsigned bytes) {
    asm volatile("mbarrier.arrive.expect_tx.shared.b64 _, [%0], %1;" :: "r"(a), "r"(bytes) : "memory");
}
__device__ __forceinline__ void mbar_wait(unsigned a, unsigned parity) {
    asm volatile(
        "{\n\t.reg .pred P;\n\t"
        "WL_%=:\n\t"
        "mbarrier.try_wait.parity.acquire.cta.shared::cta.b64 P, [%0], %1, 0x989680;\n\t"
        "@P bra.uni WD_%=;\n\t"
        "bra.uni WL_%=;\n\t"
        "WD_%=:\n\t}"
        :: "r"(a), "r"(parity) : "memory");
}
__device__ __forceinline__ void bulk_g2s(unsigned sdst, const void* gsrc, unsigned bytes, unsigned mbar) {
    asm volatile("cp.async.bulk.shared::cluster.global.mbarrier::complete_tx::bytes [%0], [%1], %2, [%3];"
                 :: "r"(sdst), "l"(gsrc), "r"(bytes), "r"(mbar) : "memory");
}
__device__ __forceinline__ void ldsm4(unsigned* r, unsigned addr) {
    asm volatile("ldmatrix.sync.aligned.m8n8.x4.shared.b16 {%0,%1,%2,%3}, [%4];"
                 : "=r"(r[0]), "=r"(r[1]), "=r"(r[2]), "=r"(r[3]) : "r"(addr));
}
__device__ __forceinline__ void mma16816(float* d, const unsigned* a, unsigned b0, unsigned b1) {
    asm volatile(
        "mma.sync.aligned.m16n8k16.row.col.f32.f16.f16.f32 "
        "{%0,%1,%2,%3}, {%4,%5,%6,%7}, {%8,%9}, {%0,%1,%2,%3};"
        : "+f"(d[0]), "+f"(d[1]), "+f"(d[2]), "+f"(d[3])
        : "r"(a[0]), "r"(a[1]), "r"(a[2]), "r"(a[3]), "r"(b0), "r"(b1));
}
__device__ __forceinline__ float sigm(float x) { return 1.f / (1.f + __expf(-x)); }
__device__ __forceinline__ float tanh_fast(float x) {
    float e = __expf(2.f * x);
    return 1.f - 2.f / (e + 1.f);
}

// ---------------------------------------------------------------------------
// Zero h buffer 0 (fragment image) and flags
// ---------------------------------------------------------------------------
__global__ void k_zero() {
    int i = blockIdx.x * blockDim.x + threadIdx.x;
    if (i < HF_BUF) g_hf[i] = make_uint4(0u, 0u, 0u, 0u);
    if (i < 16) g_donec[i] = 0u;
}

// ---------------------------------------------------------------------------
// Prep: x -> fp16 block images; W_ih -> fp16 block images (swizzled)
// ---------------------------------------------------------------------------
#define NXSEG (32768 * 64)
#define NWSEG (4096 * 64)
__global__ __launch_bounds__(256)
void k_prep(const float* __restrict__ x, const float* __restrict__ Wih) {
    int s0 = blockIdx.x * blockDim.x + threadIdx.x;
    const int stride = gridDim.x * blockDim.x;
    for (int s = s0; s < NXSEG + NWSEG; s += stride) {
        const float* src;
        char* dst;
        unsigned off;
        if (s < NXSEG) {
            int m  = s >> 6;
            int sk = s & 63;
            int b = m & 63, t = m >> 6;
            src = x + ((size_t)b * TT + t) * ISZ + sk * 8;
            int mt = m >> 7, ml = m & 127, kc = sk >> 3, seg = sk & 7;
            off = (unsigned)(mt * 8 + kc) * 16384u + (unsigned)ml * 128u
                + (unsigned)((seg ^ (ml & 7)) * 16);
            dst = (char*)g_x16;
        } else {
            int sw = s - NXSEG;
            int n  = sw >> 6;
            int sk = sw & 63;
            src = Wih + (size_t)n * ISZ + sk * 8;
            int nt = n >> 7, nl = n & 127, kc = sk >> 3, seg = sk & 7;
            off = (unsigned)(nt * 8 + kc) * 16384u + (unsigned)nl * 128u
                + (unsigned)((seg ^ (nl & 7)) * 16);
            dst = (char*)g_w16;
        }
        float4 v0 = *(const float4*)(src);
        float4 v1 = *(const float4*)(src + 4);
        uint4 hi = make_uint4(pkh(v0.x, v0.y), pkh(v0.z, v0.w),
                              pkh(v1.x, v1.y), pkh(v1.z, v1.w));
        *(uint4*)(dst + off) = hi;
    }
}

// ---------------------------------------------------------------------------
// Input GEMM via mma.sync fp16 (single product), 2-stage pipeline (R14).
// ---------------------------------------------------------------------------
#define IG_STAGE  32768
#define IG_SMEM  (2 * IG_STAGE + 512)
__global__ __launch_bounds__(256, 2)
void k_input_mma(const float* __restrict__ bih, const float* __restrict__ bhh) {
    extern __shared__ __align__(16) char smem[];
    const unsigned sb = smem_u32(smem);
    float* sbias = (float*)(smem + 2 * IG_STAGE);
    __shared__ __align__(8) u64 s_mbar[2];

    const int nt = blockIdx.x;
    const int mt = blockIdx.y;
    const int tid  = threadIdx.x;
    const int w    = tid >> 5;
    const int lane = tid & 31;
    const int wgate = (w >> 1) * 32;
    const int wm    = (w & 1) * 64;

    if (tid < 128) {
        int n = nt * 128 + tid;
        sbias[tid] = bih[n] + bhh[n];
    }
    if (tid == 0) { mbar_init(smem_u32(&s_mbar[0]), 1); mbar_init(smem_u32(&s_mbar[1]), 1); }
    __syncthreads();
    unsigned mb[2] = { smem_u32(&s_mbar[0]), smem_u32(&s_mbar[1]) };
    unsigned ph[2] = {0u, 0u};

    auto issue = [&](int kc) {
        int st = kc & 1;
        unsigned base = sb + (unsigned)st * IG_STAGE;
        size_t woff = ((size_t)nt * 8 + kc) * 16384;
        size_t xoff = ((size_t)mt * 8 + kc) * 16384;
        mbar_expect(mb[st], IG_STAGE);
        bulk_g2s(base,          (const char*)g_w16 + woff, 16384u, mb[st]);
        bulk_g2s(base + 16384u, (const char*)g_x16 + xoff, 16384u, mb[st]);
    };
    if (tid == 0) { issue(0); issue(1); }

    float d[2][8][4];
#pragma unroll
    for (int i = 0; i < 2; ++i)
#pragma unroll
        for (int j = 0; j < 8; ++j)
#pragma unroll
            for (int r = 0; r < 4; ++r) d[i][j][r] = 0.f;

    const int rA0 = wgate + (lane & 15);
    const int rA1 = rA0 + 16;
    const unsigned aSegSel = (unsigned)((lane >> 4) & 1);
    const int rBbase = wm + (lane & 7) + ((lane >> 4) & 1) * 8;
    const unsigned bSegSel = (unsigned)((lane >> 3) & 1);

    for (int kc = 0; kc < 8; ++kc) {
        const int st = kc & 1;
        mbar_wait(mb[st], ph[st] & 1u);
        ph[st]++;
        unsigned base = sb + (unsigned)st * IG_STAGE;
        unsigned Aim = base, Bim = base + 16384u;
#pragma unroll
        for (int ks = 0; ks < 4; ++ks) {
            unsigned Ah0[4], Ah1[4];
            unsigned segA0 = ((unsigned)(ks * 2) + aSegSel);
            ldsm4(Ah0, Aim + (unsigned)rA0 * 128u + ((segA0 ^ (unsigned)(rA0 & 7)) << 4));
            ldsm4(Ah1, Aim + (unsigned)rA1 * 128u + ((segA0 ^ (unsigned)(rA1 & 7)) << 4));
#pragma unroll
            for (int np = 0; np < 4; ++np) {
                int rB = rBbase + np * 16;
                unsigned segB = ((unsigned)(ks * 2) + bSegSel) ^ (unsigned)(rB & 7);
                unsigned Bh[4];
                ldsm4(Bh, Bim + (unsigned)rB * 128u + (segB << 4));
                mma16816(d[0][np * 2],     Ah0, Bh[0], Bh[1]);
                mma16816(d[0][np * 2 + 1], Ah0, Bh[2], Bh[3]);
                mma16816(d[1][np * 2],     Ah1, Bh[0], Bh[1]);
                mma16816(d[1][np * 2 + 1], Ah1, Bh[2], Bh[3]);
            }
        }
        __syncthreads();
        if (kc + 2 < 8 && tid == 0) issue(kc + 2);
    }

    // epilogue: write gx in fragment order (batch-split mapping)
    const int fg  = lane >> 2;
    const int tig = lane & 3;
#pragma unroll
    for (int mt2 = 0; mt2 < 2; ++mt2) {
#pragma unroll
        for (int rr = 0; rr < 2; ++rr) {
            int row = wgate + mt2 * 16 + fg + rr * 8;
            int n = nt * 128 + row;
            int gate = n >> 10, junit = n & 1023;
            int jtv = junit >> 4, jl = junit & 15;
            int w2 = jl >> 3, fgl = jl & 7;
            float bias = sbias[row];
#pragma unroll
            for (int j = 0; j < 8; ++j) {
                int mcol = wm + (j >> 1) * 16 + (j & 1) * 8 + tig * 2;
                int tt = mt * 2 + (mcol >> 6);
                int b  = mcol & 63;
                int q  = b >> 5, bl = b & 31;
                int wb = bl >> 4, rem = bl & 15;
                int ntv = rem >> 3, tigl = (rem >> 1) & 3;
                int cta  = jtv * 2 + q;
                int slot = (wb * 2 + w2) * 32 + fgl * 4 + tigl;
                size_t idx = ((((size_t)tt * 128 + cta) * 4 + gate) * 2 + ntv) * 128 + slot;
                ((float2*)g_gxf)[idx] = make_float2(d[mt2][j][rr * 2] + bias,
                                                    d[mt2][j][rr * 2 + 1] + bias);
            }
        }
    }
}

// ---------------------------------------------------------------------------
// SMEM layout for k_lstm: W only: 64 x (1024 fp16 + 8 pad) stride 2064
// ---------------------------------------------------------------------------
#define W_STRIDE   2064
#define SMEM_TOTAL 132096

// ---------------------------------------------------------------------------
// Persistent tensor-core LSTM, batch-split, DIRECT-LDG B path.
// CTA (jt, q) owns units [16jt,16jt+16) x 4 gates x batches [32q,32q+32).
// h lives in global as per-(q,wb,chunk,ks,lane) MMA B-fragment uint4s;
// consumers LDG.cg their exact fragments (rolling 1-chunk prefetch), no
// TMA/mbar/SMEM-B. Sync: R14 RMW counters, per-warp publish (32/chunk/step).
// No __syncthreads in the step loop.
// ---------------------------------------------------------------------------
__global__ __launch_bounds__(NTHR, 1)
void k_lstm(const float* __restrict__ Whh) {
    extern __shared__ __align__(16) char smem[];
    const unsigned sb = smem_u32(smem);

    const int bid  = blockIdx.x;
    const int jt   = bid >> 1;           // 0..63
    const int q    = bid & 1;            // batch half
    const int tid  = threadIdx.x;
    const int w    = tid >> 5;
    const int lane = tid & 31;
    const int kw   = jt >> 3;            // chunk this CTA produces into
    const int cta  = jt * 2 + q;

    // ---- one-time: W_hh rows -> SMEM fp16 (row lr = gate*16 + jl) ----
#pragma unroll
    for (int it = 0; it < 128; ++it) {
        int f   = tid + it * NTHR;       // 16384 float4
        int row = f >> 8;                // 0..63
        int k4  = (f & 255) << 2;
        int gate = row >> 4, jl = row & 15;
        const float* src = Whh + (size_t)(gate * HSZ + jt * 16 + jl) * HSZ + k4;
        float4 v = *(const float4*)src;
        uint2 hi = make_uint2(pkh(v.x, v.y), pkh(v.z, v.w));
        *(uint2*)(smem + (size_t)row * W_STRIDE + k4 * 2) = hi;
    }
    __syncthreads();

    const int w2 = w & 1, wb = w >> 1;
    const int jj0 = w2 * 8;
    // A: scattered rows (gate-interleaved): tile0 rows = gate{0,1} of jj0+(lane&7)
    const unsigned aRow  = (unsigned)(((lane >> 3) & 1) * 16 + jj0 + (lane & 7));
    const unsigned aBase = sb + aRow * W_STRIDE + ((lane >> 4) & 1) * 16u;

    const int fg  = lane >> 2;           // jj = jj0 + fg owned by this thread
    const int tig = lane & 3;
    float cc[4] = {0.f, 0.f, 0.f, 0.f};  // cells: [nt*2+e], b_local = 16wb+8nt+2tig+e

    // B fragment source base (uint4 units): [par][q][wb][c][ks][lane]
    const uint4* const hfb = g_hf + (size_t)q * HF_Q + (size_t)wb * HF_WB + lane;

    // producer h store byte-offsets for the 4 cells (into g_hf, + par*128KB)
    unsigned hoffB[4];
    {
        const int kk = jj0 + fg;                 // k within 16-unit group
        const int ks = jt & 7;
#pragma unroll
        for (int m = 0; m < 4; ++m) {
            int nt2 = m >> 1, e = m & 1;
            int lane_dst = (tig * 2 + e) * 4 + ((kk & 7) >> 1);
            int reg  = nt2 * 2 + (kk >= 8 ? 1 : 0);
            int half = kk & 1;
            unsigned idx4 = (unsigned)(q * HF_Q + wb * HF_WB + kw * HF_C + ks * HF_KS + lane_dst);
            hoffB[m] = idx4 * 16u + (unsigned)reg * 4u + (unsigned)half * 2u;
        }
    }

    unsigned* const flags_q = &g_donec[q];   // flags at [c*2+q]

    for (int t = 0; t < TT; ++t) {
        const int par = t & 1;
        const unsigned tgt = 32u * (unsigned)t;

        // ---- gx prefetch (fragment order, 8 coalesced LDG.64) ----
        float2 gxv[8];
        {
            const float2* gbase = (const float2*)g_gxf + ((size_t)t * 128 + cta) * 8 * 128 + tid;
#pragma unroll
            for (int gn = 0; gn < 8; ++gn) gxv[gn] = gbase[gn * 128];
        }

        const uint4* hb = hfb + (size_t)par * HF_BUF;

        float d[2][2][4];
#pragma unroll
        for (int mt = 0; mt < 2; ++mt)
#pragma unroll
            for (int nt2 = 0; nt2 < 2; ++nt2)
#pragma unroll
                for (int r = 0; r < 4; ++r) d[mt][nt2][r] = 0.f;

        // ---- chunk 0: wait + load fragments ----
        while (flag_acq(flags_q + 0) < tgt) { }
        uint4 Bv[8];
#pragma unroll
        for (int ks = 0; ks < 8; ++ks) Bv[ks] = ldcg4(hb + ks * HF_KS);

        for (int c = 0; c < 8; ++c) {
            if (c < 7)
                while (flag_acq(flags_q + (c + 1) * 2) < tgt) { }
            const unsigned ahi  = aBase + (unsigned)c * 256u;
            const unsigned ahi2 = ahi + 32u * W_STRIDE;
            const uint4* hbn = hb + (size_t)(c + 1) * HF_C;
#pragma unroll
            for (int ks = 0; ks < 8; ++ks) {
                uint4 B = Bv[ks];
                if (c < 7) Bv[ks] = ldcg4(hbn + ks * HF_KS);   // rolling prefetch
                unsigned A0[4], A1[4];
                ldsm4(A0, ahi  + ks * 32u);
                ldsm4(A1, ahi2 + ks * 32u);
                mma16816(d[0][0], A0, B.x, B.y);
                mma16816(d[0][1], A0, B.z, B.w);
                mma16816(d[1][0], A1, B.x, B.y);
                mma16816(d[1][1], A1, B.z, B.w);
            }
        }

        // ---- register-resident activations (4 cells) ----
        char* hwbase = (char*)g_hf + (size_t)((t + 1) & 1) * (HF_BUF * 16);
#pragma unroll
        for (int nt2 = 0; nt2 < 2; ++nt2) {
#pragma unroll
            for (int e = 0; e < 2; ++e) {
                int m = nt2 * 2 + e;
                float gi = d[0][nt2][e]     + (e ? gxv[0 + nt2].y : gxv[0 + nt2].x);
                float gf = d[0][nt2][2 + e] + (e ? gxv[2 + nt2].y : gxv[2 + nt2].x);
                float gg = d[1][nt2][e]     + (e ? gxv[4 + nt2].y : gxv[4 + nt2].x);
                float go = d[1][nt2][2 + e] + (e ? gxv[6 + nt2].y : gxv[6 + nt2].x);
                float si = sigm(gi), sf = sigm(gf), so = sigm(go);
                cc[m] = sf * cc[m] + si * tanh_fast(gg);
                float hv = so * tanh_fast(cc[m]);
                *(__half*)(hwbase + hoffB[m]) = __float2half_rn(hv);
                if (t == TT - 1) {
                    int bl = wb * 16 + nt2 * 8 + tig * 2 + e;
                    g_hfin[(size_t)(32 * q + bl) * HSZ + jt * 16 + jj0 + fg] = hv;
                }
            }
        }

        // ---- per-warp publish (release orders the STGs after syncwarp) ----
        __syncwarp();
        if (lane == 0) flag_rel(&g_donec[kw * 2 + q]);
    }
}

// ---------------------------------------------------------------------------
// Classifier
// ---------------------------------------------------------------------------
__global__ __launch_bounds__(128)
void k_classifier(const float* __restrict__ Wclf,
                  const float* __restrict__ bclf,
                  float* __restrict__ out) {
    int b = blockIdx.x;
    int o = threadIdx.x;
    __shared__ float hsh[HSZ];
    for (int k = threadIdx.x; k < HSZ; k += 128) hsh[k] = g_hfin[(size_t)b * HSZ + k];
    __syncthreads();
    const float* wp = Wclf + (size_t)o * HSZ;
    float acc = 0.f;
#pragma unroll 4
    for (int k = 0; k < HSZ; k += 4) {
        float4 wv = *(const float4*)(wp + k);
        acc += wv.x * hsh[k] + wv.y * hsh[k + 1] + wv.z * hsh[k + 2] + wv.w * hsh[k + 3];
    }
    out[b * OSZ + o] = acc + bclf[o];
}

// ---------------------------------------------------------------------------
// Launch (graph-capturable: kernel launches only)
// ---------------------------------------------------------------------------
extern "C" void kernel_launch(void* const* d_in, const int* in_sizes, int n_in,
                              void* d_out, int out_size) {
    const float* x    = (const float*)d_in[0];
    const float* Wih  = (const float*)d_in[1];
    const float* Whh  = (const float*)d_in[2];
    const float* bih  = (const float*)d_in[3];
    const float* bhh  = (const float*)d_in[4];
    const float* Wclf = (const float*)d_in[5];
    const float* bclf = (const float*)d_in[6];
    float* out = (float*)d_out;

    cudaFuncSetAttribute(k_input_mma, cudaFuncAttributeMaxDynamicSharedMemorySize, IG_SMEM);
    cudaFuncSetAttribute(k_lstm,      cudaFuncAttributeMaxDynamicSharedMemorySize, SMEM_TOTAL);

    k_zero<<<256, 256>>>();
    k_prep<<<2304, 256>>>(x, Wih);
    k_input_mma<<<dim3(32, 256), 256, IG_SMEM>>>(bih, bhh);
    k_lstm<<<NCTA, NTHR, SMEM_TOTAL>>>(Whh);
    k_classifier<<<64, 128>>>(Wclf, bclf, out);
}

// round 17
// speedup vs baseline: 1.4842x; 1.2596x over previous
#include <cuda_runtime.h>
#include <cuda_fp16.h>
#include <cstdint>
#include <cstddef>

// Problem constants
#define BSZ 64
#define TT  512
#define ISZ 512
#define HSZ 1024
#define G4  4096
#define OSZ 128
#define NCTA 128
#define NTHR 128

typedef unsigned long long u64;

// ---------------------------------------------------------------------------
// Static device scratch
// g_gxf : x-gates fragment order: [t][cta(128)][gate(4)][nt(2)][slot(128)] float2
// g_hf  : h fp16 in MMA B-FRAGMENT order:
//         uint4[buf(2)][q(2)][wb(2)][chunk(8)][ks(8)][lane(32)]
// g_x16 : x fp16 block images [mt(256)*8+kc][m(128)][k(64)] swizzled
// g_w16 : W_ih fp16 block images [nt(32)*8+kc][n(128)][k(64)] swizzled
// ---------------------------------------------------------------------------
__device__ __align__(16) float  g_gxf[(size_t)TT * 128 * 4 * 2 * 128 * 2];
__device__ __align__(16) uint4  g_hf[2 * 2 * 2 * 8 * 8 * 32];     // 256KB
__device__ __align__(16) __half g_x16[(size_t)2048 * 8192];
__device__ __align__(16) __half g_w16[(size_t)256 * 8192];
__device__ __align__(16) float  g_hfin[BSZ * HSZ];
__device__ unsigned g_donec[16];   // per (chunk, q) publish counters (32/step)

// strides for g_hf in uint4 units
#define HF_BUF 8192
#define HF_Q   4096
#define HF_WB  2048
#define HF_C   256
#define HF_KS  32

// ---------------------------------------------------------------------------
// Helpers
// ---------------------------------------------------------------------------
__device__ __forceinline__ unsigned pkh(float a, float b) {   // low=h(a), high=h(b)
    unsigned r; asm("cvt.rn.f16x2.f32 %0, %1, %2;" : "=r"(r) : "f"(b), "f"(a)); return r;
}
__device__ __forceinline__ unsigned smem_u32(const void* p) {
    unsigned a;
    asm("{ .reg .u64 t; cvta.to.shared.u64 t, %1; cvt.u32.u64 %0, t; }" : "=r"(a) : "l"(p));
    return a;
}
__device__ __forceinline__ void flag_rel(unsigned* f) {
    asm volatile("red.release.gpu.global.add.u32 [%0], %1;" :: "l"(f), "r"(1u) : "memory");
}
__device__ __forceinline__ unsigned flag_acq(const unsigned* f) {
    unsigned v;
    asm volatile("ld.acquire.gpu.global.u32 %0, [%1];" : "=r"(v) : "l"(f) : "memory");
    return v;
}
__device__ __forceinline__ uint4 ldcg4(const uint4* p) {
    uint4 v;
    asm volatile("ld.global.cg.v4.u32 {%0,%1,%2,%3}, [%4];"
                 : "=r"(v.x), "=r"(v.y), "=r"(v.z), "=r"(v.w) : "l"(p));
    return v;
}
__device__ __forceinline__ void mbar_init(unsigned a, unsigned cnt) {
    asm volatile("mbarrier.init.shared.b64 [%0], %1;" :: "r"(a), "r"(cnt) : "memory");
}
__device__ __forceinline__ void mbar_expect(unsigned a, unsigned bytes) {
    asm volatile("mbarrier.arrive.expect_tx.shared.b64 _, [%0], %1;" :: "r"(a), "r"(bytes) : "memory");
}
__device__ __forceinline__ void mbar_wait(unsigned a, unsigned parity) {
    asm volatile(
        "{\n\t.reg .pred P;\n\t"
        "WL_%=:\n\t"
        "mbarrier.try_wait.parity.acquire.cta.shared::cta.b64 P, [%0], %1, 0x989680;\n\t"
        "@P bra.uni WD_%=;\n\t"
        "bra.uni WL_%=;\n\t"
        "WD_%=:\n\t}"
        :: "r"(a), "r"(parity) : "memory");
}
__device__ __forceinline__ void bulk_g2s(unsigned sdst, const void* gsrc, unsigned bytes, unsigned mbar) {
    asm volatile("cp.async.bulk.shared::cluster.global.mbarrier::complete_tx::bytes [%0], [%1], %2, [%3];"
                 :: "r"(sdst), "l"(gsrc), "r"(bytes), "r"(mbar) : "memory");
}
__device__ __forceinline__ void ldsm4(unsigned* r, unsigned addr) {
    asm volatile("ldmatrix.sync.aligned.m8n8.x4.shared.b16 {%0,%1,%2,%3}, [%4];"
                 : "=r"(r[0]), "=r"(r[1]), "=r"(r[2]), "=r"(r[3]) : "r"(addr));
}
__device__ __forceinline__ void mma16816(float* d, const unsigned* a, unsigned b0, unsigned b1) {
    asm volatile(
        "mma.sync.aligned.m16n8k16.row.col.f32.f16.f16.f32 "
        "{%0,%1,%2,%3}, {%4,%5,%6,%7}, {%8,%9}, {%0,%1,%2,%3};"
        : "+f"(d[0]), "+f"(d[1]), "+f"(d[2]), "+f"(d[3])
        : "r"(a[0]), "r"(a[1]), "r"(a[2]), "r"(a[3]), "r"(b0), "r"(b1));
}
__device__ __forceinline__ float sigm(float x) { return 1.f / (1.f + __expf(-x)); }
__device__ __forceinline__ float tanh_fast(float x) {
    float e = __expf(2.f * x);
    return 1.f - 2.f / (e + 1.f);
}

// ---------------------------------------------------------------------------
// Zero h buffer 0 (fragment image) and flags
// ---------------------------------------------------------------------------
__global__ void k_zero() {
    int i = blockIdx.x * blockDim.x + threadIdx.x;
    if (i < HF_BUF) g_hf[i] = make_uint4(0u, 0u, 0u, 0u);
    if (i < 16) g_donec[i] = 0u;
}

// ---------------------------------------------------------------------------
// Prep: x -> fp16 block images; W_ih -> fp16 block images (swizzled)
// ---------------------------------------------------------------------------
#define NXSEG (32768 * 64)
#define NWSEG (4096 * 64)
__global__ __launch_bounds__(256)
void k_prep(const float* __restrict__ x, const float* __restrict__ Wih) {
    int s0 = blockIdx.x * blockDim.x + threadIdx.x;
    const int stride = gridDim.x * blockDim.x;
    for (int s = s0; s < NXSEG + NWSEG; s += stride) {
        const float* src;
        char* dst;
        unsigned off;
        if (s < NXSEG) {
            int m  = s >> 6;
            int sk = s & 63;
            int b = m & 63, t = m >> 6;
            src = x + ((size_t)b * TT + t) * ISZ + sk * 8;
            int mt = m >> 7, ml = m & 127, kc = sk >> 3, seg = sk & 7;
            off = (unsigned)(mt * 8 + kc) * 16384u + (unsigned)ml * 128u
                + (unsigned)((seg ^ (ml & 7)) * 16);
            dst = (char*)g_x16;
        } else {
            int sw = s - NXSEG;
            int n  = sw >> 6;
            int sk = sw & 63;
            src = Wih + (size_t)n * ISZ + sk * 8;
            int nt = n >> 7, nl = n & 127, kc = sk >> 3, seg = sk & 7;
            off = (unsigned)(nt * 8 + kc) * 16384u + (unsigned)nl * 128u
                + (unsigned)((seg ^ (nl & 7)) * 16);
            dst = (char*)g_w16;
        }
        float4 v0 = *(const float4*)(src);
        float4 v1 = *(const float4*)(src + 4);
        uint4 hi = make_uint4(pkh(v0.x, v0.y), pkh(v0.z, v0.w),
                              pkh(v1.x, v1.y), pkh(v1.z, v1.w));
        *(uint4*)(dst + off) = hi;
    }
}

// ---------------------------------------------------------------------------
// Input GEMM via mma.sync fp16 (single product), 2-stage pipeline.
// ---------------------------------------------------------------------------
#define IG_STAGE  32768
#define IG_SMEM  (2 * IG_STAGE + 512)
__global__ __launch_bounds__(256, 2)
void k_input_mma(const float* __restrict__ bih, const float* __restrict__ bhh) {
    extern __shared__ __align__(16) char smem[];
    const unsigned sb = smem_u32(smem);
    float* sbias = (float*)(smem + 2 * IG_STAGE);
    __shared__ __align__(8) u64 s_mbar[2];

    const int nt = blockIdx.x;
    const int mt = blockIdx.y;
    const int tid  = threadIdx.x;
    const int w    = tid >> 5;
    const int lane = tid & 31;
    const int wgate = (w >> 1) * 32;
    const int wm    = (w & 1) * 64;

    if (tid < 128) {
        int n = nt * 128 + tid;
        sbias[tid] = bih[n] + bhh[n];
    }
    if (tid == 0) { mbar_init(smem_u32(&s_mbar[0]), 1); mbar_init(smem_u32(&s_mbar[1]), 1); }
    __syncthreads();
    unsigned mb[2] = { smem_u32(&s_mbar[0]), smem_u32(&s_mbar[1]) };
    unsigned ph[2] = {0u, 0u};

    auto issue = [&](int kc) {
        int st = kc & 1;
        unsigned base = sb + (unsigned)st * IG_STAGE;
        size_t woff = ((size_t)nt * 8 + kc) * 16384;
        size_t xoff = ((size_t)mt * 8 + kc) * 16384;
        mbar_expect(mb[st], IG_STAGE);
        bulk_g2s(base,          (const char*)g_w16 + woff, 16384u, mb[st]);
        bulk_g2s(base + 16384u, (const char*)g_x16 + xoff, 16384u, mb[st]);
    };
    if (tid == 0) { issue(0); issue(1); }

    float d[2][8][4];
#pragma unroll
    for (int i = 0; i < 2; ++i)
#pragma unroll
        for (int j = 0; j < 8; ++j)
#pragma unroll
            for (int r = 0; r < 4; ++r) d[i][j][r] = 0.f;

    const int rA0 = wgate + (lane & 15);
    const int rA1 = rA0 + 16;
    const unsigned aSegSel = (unsigned)((lane >> 4) & 1);
    const int rBbase = wm + (lane & 7) + ((lane >> 4) & 1) * 8;
    const unsigned bSegSel = (unsigned)((lane >> 3) & 1);

    for (int kc = 0; kc < 8; ++kc) {
        const int st = kc & 1;
        mbar_wait(mb[st], ph[st] & 1u);
        ph[st]++;
        unsigned base = sb + (unsigned)st * IG_STAGE;
        unsigned Aim = base, Bim = base + 16384u;
#pragma unroll
        for (int ks = 0; ks < 4; ++ks) {
            unsigned Ah0[4], Ah1[4];
            unsigned segA0 = ((unsigned)(ks * 2) + aSegSel);
            ldsm4(Ah0, Aim + (unsigned)rA0 * 128u + ((segA0 ^ (unsigned)(rA0 & 7)) << 4));
            ldsm4(Ah1, Aim + (unsigned)rA1 * 128u + ((segA0 ^ (unsigned)(rA1 & 7)) << 4));
#pragma unroll
            for (int np = 0; np < 4; ++np) {
                int rB = rBbase + np * 16;
                unsigned segB = ((unsigned)(ks * 2) + bSegSel) ^ (unsigned)(rB & 7);
                unsigned Bh[4];
                ldsm4(Bh, Bim + (unsigned)rB * 128u + (segB << 4));
                mma16816(d[0][np * 2],     Ah0, Bh[0], Bh[1]);
                mma16816(d[0][np * 2 + 1], Ah0, Bh[2], Bh[3]);
                mma16816(d[1][np * 2],     Ah1, Bh[0], Bh[1]);
                mma16816(d[1][np * 2 + 1], Ah1, Bh[2], Bh[3]);
            }
        }
        __syncthreads();
        if (kc + 2 < 8 && tid == 0) issue(kc + 2);
    }

    // epilogue: write gx in fragment order (batch-split mapping)
    const int fg  = lane >> 2;
    const int tig = lane & 3;
#pragma unroll
    for (int mt2 = 0; mt2 < 2; ++mt2) {
#pragma unroll
        for (int rr = 0; rr < 2; ++rr) {
            int row = wgate + mt2 * 16 + fg + rr * 8;
            int n = nt * 128 + row;
            int gate = n >> 10, junit = n & 1023;
            int jtv = junit >> 4, jl = junit & 15;
            int w2 = jl >> 3, fgl = jl & 7;
            float bias = sbias[row];
#pragma unroll
            for (int j = 0; j < 8; ++j) {
                int mcol = wm + (j >> 1) * 16 + (j & 1) * 8 + tig * 2;
                int tt = mt * 2 + (mcol >> 6);
                int b  = mcol & 63;
                int q  = b >> 5, bl = b & 31;
                int wb = bl >> 4, rem = bl & 15;
                int ntv = rem >> 3, tigl = (rem >> 1) & 3;
                int cta  = jtv * 2 + q;
                int slot = (wb * 2 + w2) * 32 + fgl * 4 + tigl;
                size_t idx = ((((size_t)tt * 128 + cta) * 4 + gate) * 2 + ntv) * 128 + slot;
                ((float2*)g_gxf)[idx] = make_float2(d[mt2][j][rr * 2] + bias,
                                                    d[mt2][j][rr * 2 + 1] + bias);
            }
        }
    }
}

// ---------------------------------------------------------------------------
// SMEM layout for k_lstm: W only: 64 x (1024 fp16 + 8 pad) stride 2064
// ---------------------------------------------------------------------------
#define W_STRIDE   2064
#define SMEM_TOTAL 132096

// ---------------------------------------------------------------------------
// Persistent tensor-core LSTM, batch-split, direct-LDG B path.
// Single step-start gate: lanes 0..7 of each warp poll one chunk flag each,
// then __syncwarp() (memory-ordering among participants). Chunk loop is
// gate-free with rolling 1-chunk fragment prefetch. No TMA/mbar/SMEM-B, no
// __syncthreads in the step loop. Publish: per-warp RMW (32/chunk/step).
// ---------------------------------------------------------------------------
__global__ __launch_bounds__(NTHR, 1)
void k_lstm(const float* __restrict__ Whh) {
    extern __shared__ __align__(16) char smem[];
    const unsigned sb = smem_u32(smem);

    const int bid  = blockIdx.x;
    const int jt   = bid >> 1;           // 0..63
    const int q    = bid & 1;            // batch half
    const int tid  = threadIdx.x;
    const int w    = tid >> 5;
    const int lane = tid & 31;
    const int kw   = jt >> 3;            // chunk this CTA produces into
    const int cta  = jt * 2 + q;

    // ---- one-time: W_hh rows -> SMEM fp16 (row lr = gate*16 + jl) ----
#pragma unroll
    for (int it = 0; it < 128; ++it) {
        int f   = tid + it * NTHR;       // 16384 float4
        int row = f >> 8;                // 0..63
        int k4  = (f & 255) << 2;
        int gate = row >> 4, jl = row & 15;
        const float* src = Whh + (size_t)(gate * HSZ + jt * 16 + jl) * HSZ + k4;
        float4 v = *(const float4*)src;
        uint2 hi = make_uint2(pkh(v.x, v.y), pkh(v.z, v.w));
        *(uint2*)(smem + (size_t)row * W_STRIDE + k4 * 2) = hi;
    }
    __syncthreads();

    const int w2 = w & 1, wb = w >> 1;
    const int jj0 = w2 * 8;
    // A: scattered rows (gate-interleaved): tile0 rows = gate{0,1} of jj0+(lane&7)
    const unsigned aRow  = (unsigned)(((lane >> 3) & 1) * 16 + jj0 + (lane & 7));
    const unsigned aBase = sb + aRow * W_STRIDE + ((lane >> 4) & 1) * 16u;

    const int fg  = lane >> 2;           // jj = jj0 + fg owned by this thread
    const int tig = lane & 3;
    float cc[4] = {0.f, 0.f, 0.f, 0.f};  // cells: [nt*2+e], b_local = 16wb+8nt+2tig+e

    // B fragment source base (uint4 units): [par][q][wb][c][ks][lane]
    const uint4* const hfb = g_hf + (size_t)q * HF_Q + (size_t)wb * HF_WB + lane;

    // producer h store byte-offsets for the 4 cells (into g_hf, + par*128KB)
    unsigned hoffB[4];
    {
        const int kk = jj0 + fg;                 // k within 16-unit group
        const int ks = jt & 7;
#pragma unroll
        for (int m = 0; m < 4; ++m) {
            int nt2 = m >> 1, e = m & 1;
            int lane_dst = (tig * 2 + e) * 4 + ((kk & 7) >> 1);
            int reg  = nt2 * 2 + (kk >= 8 ? 1 : 0);
            int half = kk & 1;
            unsigned idx4 = (unsigned)(q * HF_Q + wb * HF_WB + kw * HF_C + ks * HF_KS + lane_dst);
            hoffB[m] = idx4 * 16u + (unsigned)reg * 4u + (unsigned)half * 2u;
        }
    }

    // gate flag for lanes 0..7: chunk = lane, half q
    unsigned* const gate_flag = (lane < 8) ? &g_donec[lane * 2 + q] : &g_donec[q];

    for (int t = 0; t < TT; ++t) {
        const int par = t & 1;
        const unsigned tgt = 32u * (unsigned)t;

        // ---- gx prefetch (independent of flags; overlaps the gate) ----
        float2 gxv[8];
        {
            const float2* gbase = (const float2*)g_gxf + ((size_t)t * 128 + cta) * 8 * 128 + tid;
#pragma unroll
            for (int gn = 0; gn < 8; ++gn) gxv[gn] = gbase[gn * 128];
        }

        // ---- step-start gate: lanes 0..7 each poll one chunk flag ----
        if (t && lane < 8)
            while (flag_acq(gate_flag) < tgt) { }
        __syncwarp();

        const uint4* hb = hfb + (size_t)par * HF_BUF;

        float d[2][2][4];
#pragma unroll
        for (int mt = 0; mt < 2; ++mt)
#pragma unroll
            for (int nt2 = 0; nt2 < 2; ++nt2)
#pragma unroll
                for (int r = 0; r < 4; ++r) d[mt][nt2][r] = 0.f;

        // ---- chunk 0 fragments ----
        uint4 Bv[8];
#pragma unroll
        for (int ks = 0; ks < 8; ++ks) Bv[ks] = ldcg4(hb + ks * HF_KS);

        for (int c = 0; c < 8; ++c) {
            const unsigned ahi  = aBase + (unsigned)c * 256u;
            const unsigned ahi2 = ahi + 32u * W_STRIDE;
            const uint4* hbn = hb + (size_t)(c + 1) * HF_C;
#pragma unroll
            for (int ks = 0; ks < 8; ++ks) {
                uint4 B = Bv[ks];
                if (c < 7) Bv[ks] = ldcg4(hbn + ks * HF_KS);   // rolling prefetch
                unsigned A0[4], A1[4];
                ldsm4(A0, ahi  + ks * 32u);
                ldsm4(A1, ahi2 + ks * 32u);
                mma16816(d[0][0], A0, B.x, B.y);
                mma16816(d[0][1], A0, B.z, B.w);
                mma16816(d[1][0], A1, B.x, B.y);
                mma16816(d[1][1], A1, B.z, B.w);
            }
        }

        // ---- register-resident activations (4 cells) ----
        char* hwbase = (char*)g_hf + (size_t)((t + 1) & 1) * (HF_BUF * 16);
#pragma unroll
        for (int nt2 = 0; nt2 < 2; ++nt2) {
#pragma unroll
            for (int e = 0; e < 2; ++e) {
                int m = nt2 * 2 + e;
                float gi = d[0][nt2][e]     + (e ? gxv[0 + nt2].y : gxv[0 + nt2].x);
                float gf = d[0][nt2][2 + e] + (e ? gxv[2 + nt2].y : gxv[2 + nt2].x);
                float gg = d[1][nt2][e]     + (e ? gxv[4 + nt2].y : gxv[4 + nt2].x);
                float go = d[1][nt2][2 + e] + (e ? gxv[6 + nt2].y : gxv[6 + nt2].x);
                float si = sigm(gi), sf = sigm(gf), so = sigm(go);
                cc[m] = sf * cc[m] + si * tanh_fast(gg);
                float hv = so * tanh_fast(cc[m]);
                *(__half*)(hwbase + hoffB[m]) = __float2half_rn(hv);
                if (t == TT - 1) {
                    int bl = wb * 16 + nt2 * 8 + tig * 2 + e;
                    g_hfin[(size_t)(32 * q + bl) * HSZ + jt * 16 + jj0 + fg] = hv;
                }
            }
        }

        // ---- per-warp publish (release orders the STGs after syncwarp) ----
        __syncwarp();
        if (lane == 0) flag_rel(&g_donec[kw * 2 + q]);
    }
}

// ---------------------------------------------------------------------------
// Classifier
// ---------------------------------------------------------------------------
__global__ __launch_bounds__(128)
void k_classifier(const float* __restrict__ Wclf,
                  const float* __restrict__ bclf,
                  float* __restrict__ out) {
    int b = blockIdx.x;
    int o = threadIdx.x;
    __shared__ float hsh[HSZ];
    for (int k = threadIdx.x; k < HSZ; k += 128) hsh[k] = g_hfin[(size_t)b * HSZ + k];
    __syncthreads();
    const float* wp = Wclf + (size_t)o * HSZ;
    float acc = 0.f;
#pragma unroll 4
    for (int k = 0; k < HSZ; k += 4) {
        float4 wv = *(const float4*)(wp + k);
        acc += wv.x * hsh[k] + wv.y * hsh[k + 1] + wv.z * hsh[k + 2] + wv.w * hsh[k + 3];
    }
    out[b * OSZ + o] = acc + bclf[o];
}

// ---------------------------------------------------------------------------
// Launch (graph-capturable: kernel launches only)
// ---------------------------------------------------------------------------
extern "C" void kernel_launch(void* const* d_in, const int* in_sizes, int n_in,
                              void* d_out, int out_size) {
    const float* x    = (const float*)d_in[0];
    const float* Wih  = (const float*)d_in[1];
    const float* Whh  = (const float*)d_in[2];
    const float* bih  = (const float*)d_in[3];
    const float* bhh  = (const float*)d_in[4];
    const float* Wclf = (const float*)d_in[5];
    const float* bclf = (const float*)d_in[6];
    float* out = (float*)d_out;

    cudaFuncSetAttribute(k_input_mma, cudaFuncAttributeMaxDynamicSharedMemorySize, IG_SMEM);
    cudaFuncSetAttribute(k_lstm,      cudaFuncAttributeMaxDynamicSharedMemorySize, SMEM_TOTAL);

    k_zero<<<256, 256>>>();
    k_prep<<<2304, 256>>>(x, Wih);
    k_input_mma<<<dim3(32, 256), 256, IG_SMEM>>>(bih, bhh);
    k_lstm<<<NCTA, NTHR, SMEM_TOTAL>>>(Whh);
    k_classifier<<<64, 128>>>(Wclf, bclf, out);
}